// round 3
// baseline (speedup 1.0000x reference)
#include <cuda_runtime.h>
#include <cstdint>

#define Bn 4
#define Tn 2048
#define Cn 1024
#define Hn 16
#define Dn 64
#define Mn (Bn * Tn)

// Scratch (static __device__ arrays: allowed, no runtime alloc)
__device__ float g_qkv[(size_t)Mn * 3 * Cn];   // [8192, 3072]
__device__ float g_att[(size_t)Mn * Cn];       // [8192, 1024]

// ---------------------------------------------------------------------------
// tf32 helpers
// ---------------------------------------------------------------------------
__device__ __forceinline__ uint32_t f32_to_tf32(float x) {
    uint32_t r;
    asm("cvt.rna.tf32.f32 %0, %1;" : "=r"(r) : "f"(x));
    return r;
}

__device__ __forceinline__ void split_tf32(float x, uint32_t& hi, uint32_t& lo) {
    hi = f32_to_tf32(x);
    float res = x - __uint_as_float(hi);
    lo = f32_to_tf32(res);
}

__device__ __forceinline__ void mma_tf32(float d[4], const uint32_t a[4], const uint32_t b[2]) {
    asm volatile(
        "mma.sync.aligned.m16n8k8.row.col.f32.tf32.tf32.f32 "
        "{%0,%1,%2,%3}, {%4,%5,%6,%7}, {%8,%9}, {%0,%1,%2,%3};"
        : "+f"(d[0]), "+f"(d[1]), "+f"(d[2]), "+f"(d[3])
        : "r"(a[0]), "r"(a[1]), "r"(a[2]), "r"(a[3]), "r"(b[0]), "r"(b[1]));
}

// ---------------------------------------------------------------------------
// GEMM + bias via 3xTF32 tensor-core mma:
//   C[M,N] = A[M,K] @ B[K,N] + bias[N]   (fp32-accurate)
// Block tile 128x128, BK=32, 256 threads = 8 warps in 2(M) x 4(N) grid,
// warp tile 64x32 = 4x4 mma tiles of m16n8k8.
// hi/lo tf32 split done ONCE at smem store (avoids per-fragment cvt storm).
// Smem strides (36 / 136) make mma fragment reads 32-bank conflict-free.
// ---------------------------------------------------------------------------
#define AS_STRIDE 36     // [m][k], m=128, k=32
#define BS_STRIDE 136    // [k][n], k=32, n=128
#define AS_ELEMS  (128 * AS_STRIDE)
#define BS_ELEMS  (32 * BS_STRIDE)
#define GEMM_SMEM_BYTES ((2 * AS_ELEMS + 2 * BS_ELEMS) * 4)

__global__ __launch_bounds__(256)
void gemm_tf32x3_bias(const float* __restrict__ A,
                      const float* __restrict__ Bm,
                      const float* __restrict__ bias,
                      float* __restrict__ Cm,
                      int M, int N, int K)
{
    extern __shared__ uint32_t smem[];
    uint32_t* As_hi = smem;
    uint32_t* As_lo = As_hi + AS_ELEMS;
    uint32_t* Bs_hi = As_lo + AS_ELEMS;
    uint32_t* Bs_lo = Bs_hi + BS_ELEMS;

    const int tid  = threadIdx.x;
    const int warp = tid >> 5;
    const int lane = tid & 31;
    const int wm   = warp >> 2;   // 0..1
    const int wn   = warp & 3;    // 0..3
    const int row0 = blockIdx.y * 128;
    const int col0 = blockIdx.x * 128;

    // global->smem assignment
    const int am = tid >> 1;           // 0..127
    const int ak = (tid & 1) * 16;     // 0 or 16
    const int bk = tid >> 3;           // 0..31
    const int bn = (tid & 7) * 16;     // 0..112

    const float* Ap = A  + (size_t)(row0 + am) * K + ak;
    const float* Bp = Bm + (size_t)bk * N + col0 + bn;

    float acc[4][4][4];
#pragma unroll
    for (int i = 0; i < 4; i++)
#pragma unroll
        for (int j = 0; j < 4; j++)
#pragma unroll
            for (int r = 0; r < 4; r++) acc[i][j][r] = 0.0f;

    // prefetch tile 0
    float4 apre[4], bpre[4];
#pragma unroll
    for (int i = 0; i < 4; i++) {
        apre[i] = *(const float4*)(Ap + i * 4);
        bpre[i] = *(const float4*)(Bp + i * 4);
    }

    const int NT = K / 32;
    const int ar = lane >> 2;    // 0..7
    const int ac = lane & 3;     // 0..3
    const int m0 = wm * 64;
    const int n0 = wn * 32;

    for (int kt = 0; kt < NT; kt++) {
        // split + store current tile
#pragma unroll
        for (int i = 0; i < 4; i++) {
            float av[4] = {apre[i].x, apre[i].y, apre[i].z, apre[i].w};
            float bv[4] = {bpre[i].x, bpre[i].y, bpre[i].z, bpre[i].w};
#pragma unroll
            for (int j = 0; j < 4; j++) {
                uint32_t hi, lo;
                split_tf32(av[j], hi, lo);
                int aidx = am * AS_STRIDE + ak + i * 4 + j;
                As_hi[aidx] = hi;
                As_lo[aidx] = lo;
                split_tf32(bv[j], hi, lo);
                int bidx = bk * BS_STRIDE + bn + i * 4 + j;
                Bs_hi[bidx] = hi;
                Bs_lo[bidx] = lo;
            }
        }
        __syncthreads();

        if (kt + 1 < NT) {   // prefetch next tile while computing
#pragma unroll
            for (int i = 0; i < 4; i++) {
                apre[i] = *(const float4*)(Ap + (kt + 1) * 32 + i * 4);
                bpre[i] = *(const float4*)(Bp + (size_t)(kt + 1) * 32 * N + i * 4);
            }
        }

#pragma unroll
        for (int ks = 0; ks < 4; ks++) {
            const int k0 = ks * 8;
            uint32_t a_hi[4][4], a_lo[4][4], b_hi[4][2], b_lo[4][2];
#pragma unroll
            for (int ni = 0; ni < 4; ni++) {
                int bb = (k0 + ac) * BS_STRIDE + n0 + ni * 8 + ar;
                b_hi[ni][0] = Bs_hi[bb];
                b_hi[ni][1] = Bs_hi[bb + 4 * BS_STRIDE];
                b_lo[ni][0] = Bs_lo[bb];
                b_lo[ni][1] = Bs_lo[bb + 4 * BS_STRIDE];
            }
#pragma unroll
            for (int mi = 0; mi < 4; mi++) {
                int ab = (m0 + mi * 16 + ar) * AS_STRIDE + k0 + ac;
                a_hi[mi][0] = As_hi[ab];
                a_hi[mi][1] = As_hi[ab + 8 * AS_STRIDE];
                a_hi[mi][2] = As_hi[ab + 4];
                a_hi[mi][3] = As_hi[ab + 8 * AS_STRIDE + 4];
                a_lo[mi][0] = As_lo[ab];
                a_lo[mi][1] = As_lo[ab + 8 * AS_STRIDE];
                a_lo[mi][2] = As_lo[ab + 4];
                a_lo[mi][3] = As_lo[ab + 8 * AS_STRIDE + 4];
            }
#pragma unroll
            for (int mi = 0; mi < 4; mi++)
#pragma unroll
                for (int ni = 0; ni < 4; ni++) {
                    mma_tf32(acc[mi][ni], a_hi[mi], b_hi[ni]);
                    mma_tf32(acc[mi][ni], a_hi[mi], b_lo[ni]);
                    mma_tf32(acc[mi][ni], a_lo[mi], b_hi[ni]);
                }
        }
        __syncthreads();
    }

    // epilogue: + bias, write fp32
#pragma unroll
    for (int mi = 0; mi < 4; mi++) {
        int r = row0 + m0 + mi * 16 + ar;
#pragma unroll
        for (int ni = 0; ni < 4; ni++) {
            int c = col0 + n0 + ni * 8 + ac * 2;
            float2 bv = *(const float2*)(&bias[c]);
            float2 o0, o1;
            o0.x = acc[mi][ni][0] + bv.x;
            o0.y = acc[mi][ni][1] + bv.y;
            o1.x = acc[mi][ni][2] + bv.x;
            o1.y = acc[mi][ni][3] + bv.y;
            *(float2*)(&Cm[(size_t)r * N + c])       = o0;
            *(float2*)(&Cm[(size_t)(r + 8) * N + c]) = o1;
        }
    }
}

// ---------------------------------------------------------------------------
// Flash attention, causal (unchanged fp32 version from round 1).
// ---------------------------------------------------------------------------
__global__ __launch_bounds__(128)
void attn_kernel(const float* __restrict__ qkv, float* __restrict__ att)
{
    __shared__ float Qs[64][64];
    __shared__ float KP[64][64];
    __shared__ float Vs[64][64];

    const int tid = threadIdx.x;
    const int tx  = tid & 15;
    const int ty  = tid >> 4;
    const int qt  = blockIdx.x;
    const int bh  = blockIdx.y;
    const int b   = bh >> 4;
    const int h   = bh & 15;
    const int q0  = qt * 64;

    const float* base = qkv + (size_t)b * Tn * (3 * Cn);

    {
        const int r  = tid >> 4;
        const int d0 = (tid & 15) * 4;
#pragma unroll
        for (int mm = 0; mm < 8; mm++) {
            int m = mm * 8 + r;
            float4 q4 = *(const float4*)(base + (size_t)(q0 + m) * (3 * Cn) + h * 64 + d0);
            int dd = d0 ^ ((m & 8) >> 1);
            *(float4*)(&Qs[m][dd]) = q4;
        }
    }

    float o[8][4];
    float mrow[8], lrow[8];
#pragma unroll
    for (int i = 0; i < 8; i++) {
        mrow[i] = -1e30f;
        lrow[i] = 0.0f;
#pragma unroll
        for (int j = 0; j < 4; j++) o[i][j] = 0.0f;
    }

    const float scale = 0.125f;
    const int m0 = ty * 8;
    const int n0 = tx * 4;
    const int qswz = ((m0 & 8) >> 1);

    for (int t = 0; t <= qt; t++) {
        const int kv0 = t * 64;
        __syncthreads();

        {
            const int r  = tid >> 4;
            const int d0 = (tid & 15) * 4;
#pragma unroll
            for (int mm = 0; mm < 8; mm++) {
                int n = mm * 8 + r;
                const float* kp = base + (size_t)(kv0 + n) * (3 * Cn) + Cn + h * 64 + d0;
                float4 k4 = *(const float4*)kp;
                KP[d0 + 0][n ^ (d0 + 0)] = k4.x;
                KP[d0 + 1][n ^ (d0 + 1)] = k4.y;
                KP[d0 + 2][n ^ (d0 + 2)] = k4.z;
                KP[d0 + 3][n ^ (d0 + 3)] = k4.w;
                float4 v4 = *(const float4*)(kp + Cn);
                *(float4*)(&Vs[n][d0]) = v4;
            }
        }
        __syncthreads();

        float s[8][4];
#pragma unroll
        for (int i = 0; i < 8; i++)
#pragma unroll
            for (int j = 0; j < 4; j++) s[i][j] = 0.0f;

#pragma unroll 4
        for (int d = 0; d < 64; d++) {
            float kb[4];
#pragma unroll
            for (int j = 0; j < 4; j++)
                kb[j] = KP[d][(n0 + j) ^ d];
#pragma unroll
            for (int i = 0; i < 8; i++) {
                float qa = Qs[m0 + i][d ^ qswz];
#pragma unroll
                for (int j = 0; j < 4; j++)
                    s[i][j] = fmaf(qa, kb[j], s[i][j]);
            }
        }

        if (t == qt) {
#pragma unroll
            for (int i = 0; i < 8; i++)
#pragma unroll
                for (int j = 0; j < 4; j++)
                    s[i][j] = (n0 + j > m0 + i) ? -1e30f : s[i][j] * scale;
        } else {
#pragma unroll
            for (int i = 0; i < 8; i++)
#pragma unroll
                for (int j = 0; j < 4; j++)
                    s[i][j] *= scale;
        }

#pragma unroll
        for (int i = 0; i < 8; i++) {
            float tm = fmaxf(fmaxf(s[i][0], s[i][1]), fmaxf(s[i][2], s[i][3]));
#pragma unroll
            for (int off = 8; off >= 1; off >>= 1)
                tm = fmaxf(tm, __shfl_xor_sync(0xffffffffu, tm, off));
            float mn   = fmaxf(mrow[i], tm);
            float corr = __expf(mrow[i] - mn);
            mrow[i] = mn;
            float rs = 0.0f;
#pragma unroll
            for (int j = 0; j < 4; j++) {
                float p = __expf(s[i][j] - mn);
                s[i][j] = p;
                rs += p;
            }
#pragma unroll
            for (int off = 8; off >= 1; off >>= 1)
                rs += __shfl_xor_sync(0xffffffffu, rs, off);
            lrow[i] = lrow[i] * corr + rs;
#pragma unroll
            for (int j = 0; j < 4; j++) o[i][j] *= corr;
        }

        __syncthreads();
#pragma unroll
        for (int i = 0; i < 8; i++)
            *(float4*)(&KP[m0 + i][n0]) = make_float4(s[i][0], s[i][1], s[i][2], s[i][3]);
        __syncthreads();

#pragma unroll 4
        for (int k = 0; k < 64; k++) {
            float4 vb = *(const float4*)(&Vs[k][n0]);
#pragma unroll
            for (int i = 0; i < 8; i++) {
                float pa = KP[m0 + i][k];
                o[i][0] = fmaf(pa, vb.x, o[i][0]);
                o[i][1] = fmaf(pa, vb.y, o[i][1]);
                o[i][2] = fmaf(pa, vb.z, o[i][2]);
                o[i][3] = fmaf(pa, vb.w, o[i][3]);
            }
        }
    }

#pragma unroll
    for (int i = 0; i < 8; i++) {
        float inv = 1.0f / lrow[i];
        int r = q0 + m0 + i;
        float4 ov = make_float4(o[i][0] * inv, o[i][1] * inv, o[i][2] * inv, o[i][3] * inv);
        *(float4*)(&att[((size_t)b * Tn + r) * Cn + h * 64 + n0]) = ov;
    }
}

// ---------------------------------------------------------------------------
extern "C" void kernel_launch(void* const* d_in, const int* in_sizes, int n_in,
                              void* d_out, int out_size)
{
    const float* x     = (const float*)d_in[0];  // [4,2048,1024]
    const float* Wqkv  = (const float*)d_in[1];  // [1024,3072]
    const float* bqkv  = (const float*)d_in[2];  // [3072]
    const float* Wproj = (const float*)d_in[3];  // [1024,1024]
    const float* bproj = (const float*)d_in[4];  // [1024]
    float* out = (float*)d_out;                  // [4,2048,1024]

    float *qkv_p = nullptr, *att_p = nullptr;
    cudaGetSymbolAddress((void**)&qkv_p, g_qkv);
    cudaGetSymbolAddress((void**)&att_p, g_att);

    cudaFuncSetAttribute(gemm_tf32x3_bias,
                         cudaFuncAttributeMaxDynamicSharedMemorySize,
                         GEMM_SMEM_BYTES);

    // 1) QKV = X @ W_qkv + b_qkv   (tensor cores, 3xTF32)
    gemm_tf32x3_bias<<<dim3((3 * Cn) / 128, Mn / 128), 256, GEMM_SMEM_BYTES>>>(
        x, Wqkv, bqkv, qkv_p, Mn, 3 * Cn, Cn);

    // 2) causal flash attention per (head, q-tile)
    attn_kernel<<<dim3(Tn / 64, Bn * Hn), 128>>>(qkv_p, att_p);

    // 3) out = att @ W_proj + b_proj  (tensor cores, 3xTF32)
    gemm_tf32x3_bias<<<dim3(Cn / 128, Mn / 128), 256, GEMM_SMEM_BYTES>>>(
        att_p, Wproj, bproj, out, Mn, Cn, Cn);
}

// round 4
// speedup vs baseline: 1.6014x; 1.6014x over previous
#include <cuda_runtime.h>
#include <cuda_bf16.h>
#include <cstdint>

#define Bn 4
#define Tn 2048
#define Cn 1024
#define Hn 16
#define Mn (Bn * Tn)

// ---------------- scratch (__device__ globals, no runtime alloc) ------------
__device__ __align__(16) float g_qkv[(size_t)Mn * 3 * Cn];
__device__ __align__(16) __nv_bfloat16 g_xhi[(size_t)Mn * Cn];
__device__ __align__(16) __nv_bfloat16 g_xlo[(size_t)Mn * Cn];
__device__ __align__(16) __nv_bfloat16 g_wqkvhi[(size_t)Cn * 3 * Cn];
__device__ __align__(16) __nv_bfloat16 g_wqkvlo[(size_t)Cn * 3 * Cn];
__device__ __align__(16) __nv_bfloat16 g_wprojhi[(size_t)Cn * Cn];
__device__ __align__(16) __nv_bfloat16 g_wprojlo[(size_t)Cn * Cn];
__device__ __align__(16) __nv_bfloat16 g_atthi[(size_t)Mn * Cn];
__device__ __align__(16) __nv_bfloat16 g_attlo[(size_t)Mn * Cn];

// ---------------- helpers ----------------------------------------------------
__device__ __forceinline__ uint32_t pk_bf16x2(float lo, float hi) {
    uint32_t r;
    asm("cvt.rn.bf16x2.f32 %0, %1, %2;" : "=r"(r) : "f"(hi), "f"(lo));
    return r;
}
__device__ __forceinline__ void ldsm4(uint32_t& r0, uint32_t& r1, uint32_t& r2,
                                      uint32_t& r3, uint32_t a) {
    asm volatile("ldmatrix.sync.aligned.m8n8.x4.shared.b16 {%0,%1,%2,%3}, [%4];"
                 : "=r"(r0), "=r"(r1), "=r"(r2), "=r"(r3) : "r"(a));
}
__device__ __forceinline__ void ldsm4t(uint32_t& r0, uint32_t& r1, uint32_t& r2,
                                       uint32_t& r3, uint32_t a) {
    asm volatile("ldmatrix.sync.aligned.m8n8.x4.trans.shared.b16 {%0,%1,%2,%3}, [%4];"
                 : "=r"(r0), "=r"(r1), "=r"(r2), "=r"(r3) : "r"(a));
}
__device__ __forceinline__ void hmma(float d[4], const uint32_t a[4], const uint32_t b[2]) {
    asm volatile(
        "mma.sync.aligned.m16n8k16.row.col.f32.bf16.bf16.f32 "
        "{%0,%1,%2,%3}, {%4,%5,%6,%7}, {%8,%9}, {%0,%1,%2,%3};"
        : "+f"(d[0]), "+f"(d[1]), "+f"(d[2]), "+f"(d[3])
        : "r"(a[0]), "r"(a[1]), "r"(a[2]), "r"(a[3]), "r"(b[0]), "r"(b[1]));
}

// ---------------- pack fp32 -> hi/lo bf16 ------------------------------------
__global__ __launch_bounds__(256)
void pack_hilo_kernel(const float4* __restrict__ in, uint2* __restrict__ ohi,
                      uint2* __restrict__ olo, int n4)
{
    int i = blockIdx.x * 256 + threadIdx.x;
    if (i >= n4) return;
    float4 v = in[i];
    uint32_t h0 = pk_bf16x2(v.x, v.y);
    uint32_t h1 = pk_bf16x2(v.z, v.w);
    float r0 = v.x - __uint_as_float(h0 << 16);
    float r1 = v.y - __uint_as_float(h0 & 0xffff0000u);
    float r2 = v.z - __uint_as_float(h1 << 16);
    float r3 = v.w - __uint_as_float(h1 & 0xffff0000u);
    ohi[i] = make_uint2(h0, h1);
    olo[i] = make_uint2(pk_bf16x2(r0, r1), pk_bf16x2(r2, r3));
}

// ---------------- bf16x3 GEMM + bias ------------------------------------------
// C[M,N](fp32) = (Ahi+Alo)@(Bhi+Blo) + bias.  Block 128x64x32, 8 warps (4Mx2N),
// warp tile 32x32.  A: [m][16 words], XOR swizzle f=(m&6)<<1 on 16B groups.
// B: [k][36 words] (144B rows).  All fragment loads via ldmatrix.
__global__ __launch_bounds__(256, 2)
void gemm_bf16x3_bias(const uint4* __restrict__ Ahi, const uint4* __restrict__ Alo,
                      const uint4* __restrict__ Bhi, const uint4* __restrict__ Blo,
                      const float* __restrict__ bias, float* __restrict__ Cm,
                      int M, int N, int K)
{
    __shared__ __align__(128) uint32_t sAhi[128 * 16], sAlo[128 * 16];
    __shared__ __align__(128) uint32_t sBhi[32 * 36],  sBlo[32 * 36];

    const int tid  = threadIdx.x;
    const int warp = tid >> 5;
    const int lane = tid & 31;
    const int wm   = warp >> 1;            // 0..3
    const int wn   = warp & 1;             // 0..1
    const int row0 = blockIdx.y * 128;
    const int col0 = blockIdx.x * 64;

    // writers
    const int am   = tid >> 1;
    const int akh  = (tid & 1) * 8;
    const int f_am = (am & 6) << 1;
    const int ai0  = am * 16 + (akh ^ f_am);
    const int ai1  = am * 16 + ((akh + 4) ^ f_am);
    const uint4* Aphi = Ahi + (size_t)(row0 + am) * (K / 8) + (tid & 1) * 2;
    const uint4* Aplo = Alo + (size_t)(row0 + am) * (K / 8) + (tid & 1) * 2;

    const int bk = tid >> 3;
    const int bsidx = bk * 9 + (tid & 7);
    const size_t bgoff = ((size_t)bk * N + col0 + (tid & 7) * 8) / 8;
    const uint4* Bphi = Bhi + bgoff;
    const uint4* Bplo = Blo + bgoff;
    const size_t bstep = (size_t)4 * N;    // 32 k-rows in uint4 units

    // ldmatrix addresses
    uint32_t bAhi = (uint32_t)__cvta_generic_to_shared(sAhi);
    uint32_t bAlo = (uint32_t)__cvta_generic_to_shared(sAlo);
    uint32_t bBhi = (uint32_t)__cvta_generic_to_shared(sBhi);
    uint32_t bBlo = (uint32_t)__cvta_generic_to_shared(sBlo);
    const int L = lane;
    const int row_a = wm * 32 + (L & 7) + ((L >> 3) & 1) * 8;
    const int fa = ((L & 7) & 6) << 1;
    const uint32_t aoff = (uint32_t)(row_a * 16 + ((4 * (L >> 4)) ^ fa)) * 4;
    const uint32_t boff = (uint32_t)(((L & 7) + ((L >> 3) & 1) * 8) * 144 +
                                     (wn * 32 + (L >> 4) * 8) * 2);

    float acc[2][4][4];
#pragma unroll
    for (int mi = 0; mi < 2; mi++)
#pragma unroll
        for (int ni = 0; ni < 4; ni++)
#pragma unroll
            for (int r = 0; r < 4; r++) acc[mi][ni][r] = 0.0f;

    const int NT = K / 32;
    uint4 pa0, pa1, pc0, pc1, pbh, pbl;
    pa0 = Aphi[0]; pa1 = Aphi[1];
    pc0 = Aplo[0]; pc1 = Aplo[1];
    pbh = Bphi[0]; pbl = Bplo[0];

    for (int kt = 0; kt < NT; kt++) {
        *(uint4*)&sAhi[ai0] = pa0;
        *(uint4*)&sAhi[ai1] = pa1;
        *(uint4*)&sAlo[ai0] = pc0;
        *(uint4*)&sAlo[ai1] = pc1;
        ((uint4*)sBhi)[bsidx] = pbh;
        ((uint4*)sBlo)[bsidx] = pbl;
        __syncthreads();

        if (kt + 1 < NT) {
            pa0 = Aphi[(kt + 1) * 4];  pa1 = Aphi[(kt + 1) * 4 + 1];
            pc0 = Aplo[(kt + 1) * 4];  pc1 = Aplo[(kt + 1) * 4 + 1];
            pbh = Bphi[(kt + 1) * bstep];
            pbl = Bplo[(kt + 1) * bstep];
        }

#pragma unroll
        for (int ks = 0; ks < 2; ks++) {
            uint32_t ax = (uint32_t)(ks * 32);       // byte XOR: k-group +8 words
            uint32_t bo = (uint32_t)(ks * 2304);     // +16 k-rows
            uint32_t a_hi[2][4], a_lo[2][4], b_hi[4][2], b_lo[4][2];
            ldsm4(a_hi[0][0], a_hi[0][1], a_hi[0][2], a_hi[0][3], (bAhi + aoff) ^ ax);
            ldsm4(a_hi[1][0], a_hi[1][1], a_hi[1][2], a_hi[1][3], (bAhi + aoff + 1024) ^ ax);
            ldsm4(a_lo[0][0], a_lo[0][1], a_lo[0][2], a_lo[0][3], (bAlo + aoff) ^ ax);
            ldsm4(a_lo[1][0], a_lo[1][1], a_lo[1][2], a_lo[1][3], (bAlo + aoff + 1024) ^ ax);
            ldsm4t(b_hi[0][0], b_hi[0][1], b_hi[1][0], b_hi[1][1], bBhi + boff + bo);
            ldsm4t(b_hi[2][0], b_hi[2][1], b_hi[3][0], b_hi[3][1], bBhi + boff + bo + 32);
            ldsm4t(b_lo[0][0], b_lo[0][1], b_lo[1][0], b_lo[1][1], bBlo + boff + bo);
            ldsm4t(b_lo[2][0], b_lo[2][1], b_lo[3][0], b_lo[3][1], bBlo + boff + bo + 32);
#pragma unroll
            for (int mi = 0; mi < 2; mi++)
#pragma unroll
                for (int ni = 0; ni < 4; ni++) {
                    hmma(acc[mi][ni], a_hi[mi], b_hi[ni]);
                    hmma(acc[mi][ni], a_hi[mi], b_lo[ni]);
                    hmma(acc[mi][ni], a_lo[mi], b_hi[ni]);
                }
        }
        __syncthreads();
    }

    const int g = lane >> 2, t = lane & 3;
#pragma unroll
    for (int mi = 0; mi < 2; mi++) {
        int row = row0 + wm * 32 + mi * 16 + g;
#pragma unroll
        for (int ni = 0; ni < 4; ni++) {
            int col = col0 + wn * 32 + ni * 8 + 2 * t;
            float2 bv = *(const float2*)&bias[col];
            float2 o0 = make_float2(acc[mi][ni][0] + bv.x, acc[mi][ni][1] + bv.y);
            float2 o1 = make_float2(acc[mi][ni][2] + bv.x, acc[mi][ni][3] + bv.y);
            *(float2*)&Cm[(size_t)row * N + col]       = o0;
            *(float2*)&Cm[(size_t)(row + 8) * N + col] = o1;
        }
    }
}

// ---------------- flash attention (fp32, causal); emits hi/lo bf16 ------------
__global__ __launch_bounds__(128)
void attn_kernel(const float* __restrict__ qkv,
                 __nv_bfloat16* __restrict__ atthi,
                 __nv_bfloat16* __restrict__ attlo)
{
    __shared__ float Qs[64][64];
    __shared__ float KP[64][64];
    __shared__ float Vs[64][64];

    const int tid = threadIdx.x;
    const int tx  = tid & 15;
    const int ty  = tid >> 4;
    const int qt  = blockIdx.x;
    const int bh  = blockIdx.y;
    const int b   = bh >> 4;
    const int h   = bh & 15;
    const int q0  = qt * 64;

    const float* base = qkv + (size_t)b * Tn * (3 * Cn);

    {
        const int r  = tid >> 4;
        const int d0 = (tid & 15) * 4;
#pragma unroll
        for (int mm = 0; mm < 8; mm++) {
            int m = mm * 8 + r;
            float4 q4 = *(const float4*)(base + (size_t)(q0 + m) * (3 * Cn) + h * 64 + d0);
            *(float4*)(&Qs[m][d0 ^ ((m & 8) >> 1)]) = q4;
        }
    }

    float o[8][4], mrow[8], lrow[8];
#pragma unroll
    for (int i = 0; i < 8; i++) {
        mrow[i] = -1e30f; lrow[i] = 0.0f;
#pragma unroll
        for (int j = 0; j < 4; j++) o[i][j] = 0.0f;
    }

    const float scale = 0.125f;
    const int m0 = ty * 8, n0 = tx * 4;
    const int qswz = ((m0 & 8) >> 1);

    for (int t = 0; t <= qt; t++) {
        const int kv0 = t * 64;
        __syncthreads();
        {
            const int r  = tid >> 4;
            const int d0 = (tid & 15) * 4;
#pragma unroll
            for (int mm = 0; mm < 8; mm++) {
                int n = mm * 8 + r;
                const float* kp = base + (size_t)(kv0 + n) * (3 * Cn) + Cn + h * 64 + d0;
                float4 k4 = *(const float4*)kp;
                KP[d0 + 0][n ^ (d0 + 0)] = k4.x;
                KP[d0 + 1][n ^ (d0 + 1)] = k4.y;
                KP[d0 + 2][n ^ (d0 + 2)] = k4.z;
                KP[d0 + 3][n ^ (d0 + 3)] = k4.w;
                *(float4*)(&Vs[n][d0]) = *(const float4*)(kp + Cn);
            }
        }
        __syncthreads();

        float s[8][4];
#pragma unroll
        for (int i = 0; i < 8; i++)
#pragma unroll
            for (int j = 0; j < 4; j++) s[i][j] = 0.0f;

#pragma unroll 4
        for (int d = 0; d < 64; d++) {
            float kb[4];
#pragma unroll
            for (int j = 0; j < 4; j++) kb[j] = KP[d][(n0 + j) ^ d];
#pragma unroll
            for (int i = 0; i < 8; i++) {
                float qa = Qs[m0 + i][d ^ qswz];
#pragma unroll
                for (int j = 0; j < 4; j++) s[i][j] = fmaf(qa, kb[j], s[i][j]);
            }
        }

        if (t == qt) {
#pragma unroll
            for (int i = 0; i < 8; i++)
#pragma unroll
                for (int j = 0; j < 4; j++)
                    s[i][j] = (n0 + j > m0 + i) ? -1e30f : s[i][j] * scale;
        } else {
#pragma unroll
            for (int i = 0; i < 8; i++)
#pragma unroll
                for (int j = 0; j < 4; j++) s[i][j] *= scale;
        }

#pragma unroll
        for (int i = 0; i < 8; i++) {
            float tm = fmaxf(fmaxf(s[i][0], s[i][1]), fmaxf(s[i][2], s[i][3]));
#pragma unroll
            for (int off = 8; off >= 1; off >>= 1)
                tm = fmaxf(tm, __shfl_xor_sync(0xffffffffu, tm, off));
            float mn = fmaxf(mrow[i], tm);
            float corr = __expf(mrow[i] - mn);
            mrow[i] = mn;
            float rs = 0.0f;
#pragma unroll
            for (int j = 0; j < 4; j++) {
                float p = __expf(s[i][j] - mn);
                s[i][j] = p; rs += p;
            }
#pragma unroll
            for (int off = 8; off >= 1; off >>= 1)
                rs += __shfl_xor_sync(0xffffffffu, rs, off);
            lrow[i] = lrow[i] * corr + rs;
#pragma unroll
            for (int j = 0; j < 4; j++) o[i][j] *= corr;
        }

        __syncthreads();
#pragma unroll
        for (int i = 0; i < 8; i++)
            *(float4*)(&KP[m0 + i][n0]) = make_float4(s[i][0], s[i][1], s[i][2], s[i][3]);
        __syncthreads();

#pragma unroll 4
        for (int k = 0; k < 64; k++) {
            float4 vb = *(const float4*)(&Vs[k][n0]);
#pragma unroll
            for (int i = 0; i < 8; i++) {
                float pa = KP[m0 + i][k];
                o[i][0] = fmaf(pa, vb.x, o[i][0]);
                o[i][1] = fmaf(pa, vb.y, o[i][1]);
                o[i][2] = fmaf(pa, vb.z, o[i][2]);
                o[i][3] = fmaf(pa, vb.w, o[i][3]);
            }
        }
    }

#pragma unroll
    for (int i = 0; i < 8; i++) {
        float inv = 1.0f / lrow[i];
        float o0 = o[i][0] * inv, o1 = o[i][1] * inv;
        float o2 = o[i][2] * inv, o3 = o[i][3] * inv;
        uint32_t h0 = pk_bf16x2(o0, o1);
        uint32_t h1 = pk_bf16x2(o2, o3);
        float r0 = o0 - __uint_as_float(h0 << 16);
        float r1 = o1 - __uint_as_float(h0 & 0xffff0000u);
        float r2 = o2 - __uint_as_float(h1 << 16);
        float r3 = o3 - __uint_as_float(h1 & 0xffff0000u);
        size_t idx = ((size_t)b * Tn + q0 + m0 + i) * Cn + h * 64 + n0;
        *(uint2*)&atthi[idx] = make_uint2(h0, h1);
        *(uint2*)&attlo[idx] = make_uint2(pk_bf16x2(r0, r1), pk_bf16x2(r2, r3));
    }
}

// ---------------------------------------------------------------------------
extern "C" void kernel_launch(void* const* d_in, const int* in_sizes, int n_in,
                              void* d_out, int out_size)
{
    const float* x     = (const float*)d_in[0];
    const float* Wqkv  = (const float*)d_in[1];
    const float* bqkv  = (const float*)d_in[2];
    const float* Wproj = (const float*)d_in[3];
    const float* bproj = (const float*)d_in[4];
    float* out = (float*)d_out;

    float *qkv_p;
    __nv_bfloat16 *xhi, *xlo, *wqh, *wql, *wph, *wpl, *ahi, *alo;
    cudaGetSymbolAddress((void**)&qkv_p, g_qkv);
    cudaGetSymbolAddress((void**)&xhi, g_xhi);
    cudaGetSymbolAddress((void**)&xlo, g_xlo);
    cudaGetSymbolAddress((void**)&wqh, g_wqkvhi);
    cudaGetSymbolAddress((void**)&wql, g_wqkvlo);
    cudaGetSymbolAddress((void**)&wph, g_wprojhi);
    cudaGetSymbolAddress((void**)&wpl, g_wprojlo);
    cudaGetSymbolAddress((void**)&ahi, g_atthi);
    cudaGetSymbolAddress((void**)&alo, g_attlo);

    // pack inputs to hi/lo bf16
    int nx = Mn * Cn / 4, nwq = Cn * 3 * Cn / 4, nwp = Cn * Cn / 4;
    pack_hilo_kernel<<<(nx + 255) / 256, 256>>>((const float4*)x, (uint2*)xhi, (uint2*)xlo, nx);
    pack_hilo_kernel<<<(nwq + 255) / 256, 256>>>((const float4*)Wqkv, (uint2*)wqh, (uint2*)wql, nwq);
    pack_hilo_kernel<<<(nwp + 255) / 256, 256>>>((const float4*)Wproj, (uint2*)wph, (uint2*)wpl, nwp);

    // 1) QKV = X @ W_qkv + b
    gemm_bf16x3_bias<<<dim3((3 * Cn) / 64, Mn / 128), 256>>>(
        (const uint4*)xhi, (const uint4*)xlo, (const uint4*)wqh, (const uint4*)wql,
        bqkv, qkv_p, Mn, 3 * Cn, Cn);

    // 2) causal flash attention
    attn_kernel<<<dim3(Tn / 64, Bn * Hn), 128>>>(qkv_p, ahi, alo);

    // 3) out = att @ W_proj + b
    gemm_bf16x3_bias<<<dim3(Cn / 64, Mn / 128), 256>>>(
        (const uint4*)ahi, (const uint4*)alo, (const uint4*)wph, (const uint4*)wpl,
        bproj, out, Mn, Cn, Cn);
}

// round 6
// speedup vs baseline: 3.0637x; 1.9131x over previous
#include <cuda_runtime.h>
#include <cuda_bf16.h>
#include <cstdint>

#define Bn 4
#define Tn 2048
#define Cn 1024
#define Hn 16
#define Mn (Bn * Tn)

// ---------------- scratch (__device__ globals, no runtime alloc) ------------
__device__ __align__(16) __nv_bfloat16 g_xhi[(size_t)Mn * Cn];
__device__ __align__(16) __nv_bfloat16 g_xlo[(size_t)Mn * Cn];
__device__ __align__(16) __nv_bfloat16 g_wqkvhi[(size_t)Cn * 3 * Cn];
__device__ __align__(16) __nv_bfloat16 g_wqkvlo[(size_t)Cn * 3 * Cn];
__device__ __align__(16) __nv_bfloat16 g_wprojhi[(size_t)Cn * Cn];
__device__ __align__(16) __nv_bfloat16 g_wprojlo[(size_t)Cn * Cn];
__device__ __align__(16) __nv_bfloat16 g_qkvh[(size_t)Mn * 3 * Cn];
__device__ __align__(16) __nv_bfloat16 g_qkvl[(size_t)Mn * 3 * Cn];
__device__ __align__(16) __nv_bfloat16 g_atthi[(size_t)Mn * Cn];
__device__ __align__(16) __nv_bfloat16 g_attlo[(size_t)Mn * Cn];

// ---------------- helpers ----------------------------------------------------
__device__ __forceinline__ uint32_t pk_bf16x2(float lo, float hi) {
    uint32_t r;
    asm("cvt.rn.bf16x2.f32 %0, %1, %2;" : "=r"(r) : "f"(hi), "f"(lo));
    return r;
}
__device__ __forceinline__ float bflow(uint32_t h)  { return __uint_as_float(h << 16); }
__device__ __forceinline__ float bfhigh(uint32_t h) { return __uint_as_float(h & 0xffff0000u); }

__device__ __forceinline__ void ldsm4(uint32_t& r0, uint32_t& r1, uint32_t& r2,
                                      uint32_t& r3, uint32_t a) {
    asm volatile("ldmatrix.sync.aligned.m8n8.x4.shared.b16 {%0,%1,%2,%3}, [%4];"
                 : "=r"(r0), "=r"(r1), "=r"(r2), "=r"(r3) : "r"(a));
}
__device__ __forceinline__ void ldsm4t(uint32_t& r0, uint32_t& r1, uint32_t& r2,
                                       uint32_t& r3, uint32_t a) {
    asm volatile("ldmatrix.sync.aligned.m8n8.x4.trans.shared.b16 {%0,%1,%2,%3}, [%4];"
                 : "=r"(r0), "=r"(r1), "=r"(r2), "=r"(r3) : "r"(a));
}
__device__ __forceinline__ void hmma(float d[4], const uint32_t a[4], const uint32_t b[2]) {
    asm volatile(
        "mma.sync.aligned.m16n8k16.row.col.f32.bf16.bf16.f32 "
        "{%0,%1,%2,%3}, {%4,%5,%6,%7}, {%8,%9}, {%0,%1,%2,%3};"
        : "+f"(d[0]), "+f"(d[1]), "+f"(d[2]), "+f"(d[3])
        : "r"(a[0]), "r"(a[1]), "r"(a[2]), "r"(a[3]), "r"(b[0]), "r"(b[1]));
}

// ---------------- pack fp32 -> hi/lo bf16 ------------------------------------
__global__ __launch_bounds__(256)
void pack_hilo_kernel(const float4* __restrict__ in, uint2* __restrict__ ohi,
                      uint2* __restrict__ olo, int n4)
{
    int i = blockIdx.x * 256 + threadIdx.x;
    if (i >= n4) return;
    float4 v = in[i];
    uint32_t h0 = pk_bf16x2(v.x, v.y);
    uint32_t h1 = pk_bf16x2(v.z, v.w);
    ohi[i] = make_uint2(h0, h1);
    olo[i] = make_uint2(pk_bf16x2(v.x - bflow(h0), v.y - bfhigh(h0)),
                        pk_bf16x2(v.z - bflow(h1), v.w - bfhigh(h1)));
}

// ---------------- bf16x3 GEMM (templated epilogue) -----------------------------
// C[M,N] = (Ahi+Alo)@(Bhi+Blo) + bias.  Block 128x64x32, 8 warps (4Mx2N),
// warp tile 32x32.  A smem: [m][16 words], XOR swizzle f=(m&6)<<1.
// B smem: [k][36 words] (144B rows).  All fragment loads via ldmatrix.
// OUT_MODE 0: fp32 Cm.  OUT_MODE 1: hi/lo bf16 split (Chi/Clo).
template <int OUT_MODE>
__global__ __launch_bounds__(256, 2)
void gemm_bf16x3(const uint4* __restrict__ Ahi, const uint4* __restrict__ Alo,
                 const uint4* __restrict__ Bhi, const uint4* __restrict__ Blo,
                 const float* __restrict__ bias, float* __restrict__ Cm,
                 __nv_bfloat16* __restrict__ Chi, __nv_bfloat16* __restrict__ Clo,
                 int M, int N, int K)
{
    __shared__ __align__(128) uint32_t sAhi[128 * 16], sAlo[128 * 16];
    __shared__ __align__(128) uint32_t sBhi[32 * 36],  sBlo[32 * 36];

    const int tid  = threadIdx.x;
    const int warp = tid >> 5;
    const int lane = tid & 31;
    const int wm   = warp >> 1;
    const int wn   = warp & 1;
    const int row0 = blockIdx.y * 128;
    const int col0 = blockIdx.x * 64;

    const int am   = tid >> 1;
    const int akh  = (tid & 1) * 8;
    const int f_am = (am & 6) << 1;
    const int ai0  = am * 16 + (akh ^ f_am);
    const int ai1  = am * 16 + ((akh + 4) ^ f_am);
    const uint4* Aphi = Ahi + (size_t)(row0 + am) * (K / 8) + (tid & 1) * 2;
    const uint4* Aplo = Alo + (size_t)(row0 + am) * (K / 8) + (tid & 1) * 2;

    const int bk = tid >> 3;
    const int bsidx = bk * 9 + (tid & 7);
    const size_t bgoff = ((size_t)bk * N + col0 + (tid & 7) * 8) / 8;
    const uint4* Bphi = Bhi + bgoff;
    const uint4* Bplo = Blo + bgoff;
    const size_t bstep = (size_t)4 * N;

    uint32_t bAhi = (uint32_t)__cvta_generic_to_shared(sAhi);
    uint32_t bAlo = (uint32_t)__cvta_generic_to_shared(sAlo);
    uint32_t bBhi = (uint32_t)__cvta_generic_to_shared(sBhi);
    uint32_t bBlo = (uint32_t)__cvta_generic_to_shared(sBlo);
    const int L = lane;
    const int row_a = wm * 32 + (L & 7) + ((L >> 3) & 1) * 8;
    const int fa = ((L & 7) & 6) << 1;
    const uint32_t aoff = (uint32_t)(row_a * 16 + ((4 * (L >> 4)) ^ fa)) * 4;
    const uint32_t boff = (uint32_t)(((L & 7) + ((L >> 3) & 1) * 8) * 144 +
                                     (wn * 32 + (L >> 4) * 8) * 2);

    float acc[2][4][4];
#pragma unroll
    for (int mi = 0; mi < 2; mi++)
#pragma unroll
        for (int ni = 0; ni < 4; ni++)
#pragma unroll
            for (int r = 0; r < 4; r++) acc[mi][ni][r] = 0.0f;

    const int NT = K / 32;
    uint4 pa0 = Aphi[0], pa1 = Aphi[1], pc0 = Aplo[0], pc1 = Aplo[1];
    uint4 pbh = Bphi[0], pbl = Bplo[0];

    for (int kt = 0; kt < NT; kt++) {
        *(uint4*)&sAhi[ai0] = pa0;
        *(uint4*)&sAhi[ai1] = pa1;
        *(uint4*)&sAlo[ai0] = pc0;
        *(uint4*)&sAlo[ai1] = pc1;
        ((uint4*)sBhi)[bsidx] = pbh;
        ((uint4*)sBlo)[bsidx] = pbl;
        __syncthreads();

        if (kt + 1 < NT) {
            pa0 = Aphi[(kt + 1) * 4];  pa1 = Aphi[(kt + 1) * 4 + 1];
            pc0 = Aplo[(kt + 1) * 4];  pc1 = Aplo[(kt + 1) * 4 + 1];
            pbh = Bphi[(kt + 1) * bstep];
            pbl = Bplo[(kt + 1) * bstep];
        }

#pragma unroll
        for (int ks = 0; ks < 2; ks++) {
            uint32_t ax = (uint32_t)(ks * 32);
            uint32_t bo = (uint32_t)(ks * 2304);
            uint32_t a_hi[2][4], a_lo[2][4], b_hi[4][2], b_lo[4][2];
            ldsm4(a_hi[0][0], a_hi[0][1], a_hi[0][2], a_hi[0][3], (bAhi + aoff) ^ ax);
            ldsm4(a_hi[1][0], a_hi[1][1], a_hi[1][2], a_hi[1][3], (bAhi + aoff + 1024) ^ ax);
            ldsm4(a_lo[0][0], a_lo[0][1], a_lo[0][2], a_lo[0][3], (bAlo + aoff) ^ ax);
            ldsm4(a_lo[1][0], a_lo[1][1], a_lo[1][2], a_lo[1][3], (bAlo + aoff + 1024) ^ ax);
            ldsm4t(b_hi[0][0], b_hi[0][1], b_hi[1][0], b_hi[1][1], bBhi + boff + bo);
            ldsm4t(b_hi[2][0], b_hi[2][1], b_hi[3][0], b_hi[3][1], bBhi + boff + bo + 32);
            ldsm4t(b_lo[0][0], b_lo[0][1], b_lo[1][0], b_lo[1][1], bBlo + boff + bo);
            ldsm4t(b_lo[2][0], b_lo[2][1], b_lo[3][0], b_lo[3][1], bBlo + boff + bo + 32);
#pragma unroll
            for (int mi = 0; mi < 2; mi++)
#pragma unroll
                for (int ni = 0; ni < 4; ni++) {
                    hmma(acc[mi][ni], a_hi[mi], b_hi[ni]);
                    hmma(acc[mi][ni], a_hi[mi], b_lo[ni]);
                    hmma(acc[mi][ni], a_lo[mi], b_hi[ni]);
                }
        }
        __syncthreads();
    }

    const int g = lane >> 2, t = lane & 3;
#pragma unroll
    for (int mi = 0; mi < 2; mi++) {
        int row = row0 + wm * 32 + mi * 16 + g;
#pragma unroll
        for (int ni = 0; ni < 4; ni++) {
            int col = col0 + wn * 32 + ni * 8 + 2 * t;
            float2 bv = *(const float2*)&bias[col];
            float v0 = acc[mi][ni][0] + bv.x, v1 = acc[mi][ni][1] + bv.y;
            float v2 = acc[mi][ni][2] + bv.x, v3 = acc[mi][ni][3] + bv.y;
            if (OUT_MODE == 0) {
                *(float2*)&Cm[(size_t)row * N + col]       = make_float2(v0, v1);
                *(float2*)&Cm[(size_t)(row + 8) * N + col] = make_float2(v2, v3);
            } else {
                uint32_t hh = pk_bf16x2(v0, v1);
                size_t i0 = ((size_t)row * N + col) >> 1;
                ((uint32_t*)Chi)[i0] = hh;
                ((uint32_t*)Clo)[i0] = pk_bf16x2(v0 - bflow(hh), v1 - bfhigh(hh));
                hh = pk_bf16x2(v2, v3);
                size_t i1 = ((size_t)(row + 8) * N + col) >> 1;
                ((uint32_t*)Chi)[i1] = hh;
                ((uint32_t*)Clo)[i1] = pk_bf16x2(v2 - bflow(hh), v3 - bfhigh(hh));
            }
        }
    }
}

// ---------------- tensor-core flash attention (bf16x3, causal) ----------------
// Block: 64 q-rows x (b,h). 4 warps, warp = 16 q-rows. KV tiles of 64.
// smem rows stride 72 elements (144B) -> conflict-free ldmatrix.
__global__ __launch_bounds__(128)
void attn_mma_kernel(const __nv_bfloat16* __restrict__ qh,
                     const __nv_bfloat16* __restrict__ ql,
                     __nv_bfloat16* __restrict__ atthi,
                     __nv_bfloat16* __restrict__ attlo)
{
    __shared__ __align__(16) __nv_bfloat16 sKh[64 * 72], sKl[64 * 72];
    __shared__ __align__(16) __nv_bfloat16 sVh[64 * 72], sVl[64 * 72];

    const int tid  = threadIdx.x;
    const int lane = tid & 31;
    const int warp = tid >> 5;
    const int qt   = (int)(gridDim.x - 1) - (int)blockIdx.x;  // heavy tiles first
    const int bh   = blockIdx.y;
    const int b    = bh >> 4, h = bh & 15;
    const int q0   = qt * 64;
    const int m0w  = warp * 16;
    const int g    = lane >> 2, qd = lane & 3;
    const size_t rowbase = (size_t)b * Tn;
    const int hcol = h * 64;

    const int fr = (lane & 7) + ((lane >> 3) & 1) * 8;
    const int hb = (lane >> 4) * 16;

    uint32_t sKh_b = (uint32_t)__cvta_generic_to_shared(sKh);
    uint32_t sKl_b = (uint32_t)__cvta_generic_to_shared(sKl);
    uint32_t sVh_b = (uint32_t)__cvta_generic_to_shared(sVh);
    uint32_t sVl_b = (uint32_t)__cvta_generic_to_shared(sVl);

    // ---- stage Q through sKh/sKl, load fragments into registers ----
#pragma unroll
    for (int it = 0; it < 4; it++) {
        int idx = tid + it * 128;
        int r = idx >> 3, c = idx & 7;
        size_t grow = (rowbase + q0 + r) * (3 * Cn) + hcol;
        ((uint4*)sKh)[r * 9 + c] = *((const uint4*)(qh + grow) + c);
        ((uint4*)sKl)[r * 9 + c] = *((const uint4*)(ql + grow) + c);
    }
    __syncthreads();

    uint32_t qhi[4][4], qlo[4][4];
#pragma unroll
    for (int j = 0; j < 4; j++) {
        uint32_t ad = (uint32_t)((m0w + fr) * 144 + j * 32 + hb);
        ldsm4(qhi[j][0], qhi[j][1], qhi[j][2], qhi[j][3], sKh_b + ad);
        ldsm4(qlo[j][0], qlo[j][1], qlo[j][2], qlo[j][3], sKl_b + ad);
    }

    float o[8][4];
#pragma unroll
    for (int nt = 0; nt < 8; nt++)
#pragma unroll
        for (int r = 0; r < 4; r++) o[nt][r] = 0.0f;
    float m0r = -1e30f, m1r = -1e30f, l0 = 0.0f, l1 = 0.0f;

    const float scale = 0.125f;
    const int rl0 = m0w + g, rl1 = rl0 + 8;

    for (int t = 0; t <= qt; t++) {
        const int kv0 = t * 64;
        __syncthreads();
#pragma unroll
        for (int it = 0; it < 4; it++) {
            int idx = tid + it * 128;
            int r = idx >> 3, c = idx & 7;
            size_t grow = (rowbase + kv0 + r) * (3 * Cn) + hcol;
            ((uint4*)sKh)[r * 9 + c] = *((const uint4*)(qh + grow + Cn) + c);
            ((uint4*)sKl)[r * 9 + c] = *((const uint4*)(ql + grow + Cn) + c);
            ((uint4*)sVh)[r * 9 + c] = *((const uint4*)(qh + grow + 2 * Cn) + c);
            ((uint4*)sVl)[r * 9 + c] = *((const uint4*)(ql + grow + 2 * Cn) + c);
        }
        __syncthreads();

        // ---- S = Q K^T (bf16x3) ----
        float s[8][4];
#pragma unroll
        for (int nt = 0; nt < 8; nt++)
#pragma unroll
            for (int r = 0; r < 4; r++) s[nt][r] = 0.0f;

#pragma unroll
        for (int p = 0; p < 4; p++) {
#pragma unroll
            for (int j = 0; j < 4; j++) {
                uint32_t kh0, kh1, kh2, kh3, kl0, kl1, kl2, kl3;
                uint32_t ad = (uint32_t)((p * 16 + fr) * 144 + j * 32 + hb);
                ldsm4(kh0, kh1, kh2, kh3, sKh_b + ad);
                ldsm4(kl0, kl1, kl2, kl3, sKl_b + ad);
                uint32_t b0h[2] = {kh0, kh2}, b1h[2] = {kh1, kh3};
                uint32_t b0l[2] = {kl0, kl2}, b1l[2] = {kl1, kl3};
                hmma(s[2 * p],     qhi[j], b0h);
                hmma(s[2 * p],     qhi[j], b0l);
                hmma(s[2 * p],     qlo[j], b0h);
                hmma(s[2 * p + 1], qhi[j], b1h);
                hmma(s[2 * p + 1], qhi[j], b1l);
                hmma(s[2 * p + 1], qlo[j], b1h);
            }
        }

        // ---- scale + causal mask ----
#pragma unroll
        for (int nt = 0; nt < 8; nt++) {
            s[nt][0] *= scale; s[nt][1] *= scale;
            s[nt][2] *= scale; s[nt][3] *= scale;
        }
        if (t == qt) {
#pragma unroll
            for (int nt = 0; nt < 8; nt++) {
                int c0 = nt * 8 + 2 * qd;
                if (c0     > rl0) s[nt][0] = -1e30f;
                if (c0 + 1 > rl0) s[nt][1] = -1e30f;
                if (c0     > rl1) s[nt][2] = -1e30f;
                if (c0 + 1 > rl1) s[nt][3] = -1e30f;
            }
        }

        // ---- online softmax (rows g and g+8) ----
        float mx0 = -1e30f, mx1 = -1e30f;
#pragma unroll
        for (int nt = 0; nt < 8; nt++) {
            mx0 = fmaxf(mx0, fmaxf(s[nt][0], s[nt][1]));
            mx1 = fmaxf(mx1, fmaxf(s[nt][2], s[nt][3]));
        }
        mx0 = fmaxf(mx0, __shfl_xor_sync(0xffffffffu, mx0, 1));
        mx0 = fmaxf(mx0, __shfl_xor_sync(0xffffffffu, mx0, 2));
        mx1 = fmaxf(mx1, __shfl_xor_sync(0xffffffffu, mx1, 1));
        mx1 = fmaxf(mx1, __shfl_xor_sync(0xffffffffu, mx1, 2));
        float mn0 = fmaxf(m0r, mx0), mn1 = fmaxf(m1r, mx1);
        float cf0 = __expf(m0r - mn0), cf1 = __expf(m1r - mn1);
        m0r = mn0; m1r = mn1;
        float sum0 = 0.0f, sum1 = 0.0f;
#pragma unroll
        for (int nt = 0; nt < 8; nt++) {
            s[nt][0] = __expf(s[nt][0] - mn0); sum0 += s[nt][0];
            s[nt][1] = __expf(s[nt][1] - mn0); sum0 += s[nt][1];
            s[nt][2] = __expf(s[nt][2] - mn1); sum1 += s[nt][2];
            s[nt][3] = __expf(s[nt][3] - mn1); sum1 += s[nt][3];
        }
        sum0 += __shfl_xor_sync(0xffffffffu, sum0, 1);
        sum0 += __shfl_xor_sync(0xffffffffu, sum0, 2);
        sum1 += __shfl_xor_sync(0xffffffffu, sum1, 1);
        sum1 += __shfl_xor_sync(0xffffffffu, sum1, 2);
        l0 = l0 * cf0 + sum0;
        l1 = l1 * cf1 + sum1;
#pragma unroll
        for (int nt = 0; nt < 8; nt++) {
            o[nt][0] *= cf0; o[nt][1] *= cf0;
            o[nt][2] *= cf1; o[nt][3] *= cf1;
        }

        // ---- O += P V (bf16x3), P split hi/lo in registers ----
#pragma unroll
        for (int j = 0; j < 4; j++) {
            uint32_t phi[4], plo[4];
            uint32_t hh;
            hh = pk_bf16x2(s[2 * j][0], s[2 * j][1]);
            phi[0] = hh;
            plo[0] = pk_bf16x2(s[2 * j][0] - bflow(hh), s[2 * j][1] - bfhigh(hh));
            hh = pk_bf16x2(s[2 * j][2], s[2 * j][3]);
            phi[1] = hh;
            plo[1] = pk_bf16x2(s[2 * j][2] - bflow(hh), s[2 * j][3] - bfhigh(hh));
            hh = pk_bf16x2(s[2 * j + 1][0], s[2 * j + 1][1]);
            phi[2] = hh;
            plo[2] = pk_bf16x2(s[2 * j + 1][0] - bflow(hh), s[2 * j + 1][1] - bfhigh(hh));
            hh = pk_bf16x2(s[2 * j + 1][2], s[2 * j + 1][3]);
            phi[3] = hh;
            plo[3] = pk_bf16x2(s[2 * j + 1][2] - bflow(hh), s[2 * j + 1][3] - bfhigh(hh));

#pragma unroll
            for (int p = 0; p < 4; p++) {
                uint32_t v0, v1, v2, v3, w0, w1, w2, w3;
                uint32_t ad = (uint32_t)((j * 16 + fr) * 144 + p * 32 + hb);
                ldsm4t(v0, v1, v2, v3, sVh_b + ad);
                ldsm4t(w0, w1, w2, w3, sVl_b + ad);
                uint32_t bh0[2] = {v0, v1}, bh1[2] = {v2, v3};
                uint32_t bl0[2] = {w0, w1}, bl1[2] = {w2, w3};
                hmma(o[2 * p],     phi, bh0);
                hmma(o[2 * p],     phi, bl0);
                hmma(o[2 * p],     plo, bh0);
                hmma(o[2 * p + 1], phi, bh1);
                hmma(o[2 * p + 1], phi, bl1);
                hmma(o[2 * p + 1], plo, bh1);
            }
        }
    }

    // ---- epilogue: normalize, split hi/lo, store ----
    float inv0 = 1.0f / l0, inv1 = 1.0f / l1;
    size_t orow0 = (rowbase + q0 + m0w + g) * Cn + hcol;
    size_t orow1 = orow0 + (size_t)8 * Cn;
#pragma unroll
    for (int nt = 0; nt < 8; nt++) {
        int c = nt * 8 + 2 * qd;
        float v0 = o[nt][0] * inv0, v1 = o[nt][1] * inv0;
        uint32_t hh = pk_bf16x2(v0, v1);
        ((uint32_t*)atthi)[(orow0 + c) >> 1] = hh;
        ((uint32_t*)attlo)[(orow0 + c) >> 1] =
            pk_bf16x2(v0 - bflow(hh), v1 - bfhigh(hh));
        v0 = o[nt][2] * inv1; v1 = o[nt][3] * inv1;
        hh = pk_bf16x2(v0, v1);
        ((uint32_t*)atthi)[(orow1 + c) >> 1] = hh;
        ((uint32_t*)attlo)[(orow1 + c) >> 1] =
            pk_bf16x2(v0 - bflow(hh), v1 - bfhigh(hh));
    }
}

// ---------------------------------------------------------------------------
extern "C" void kernel_launch(void* const* d_in, const int* in_sizes, int n_in,
                              void* d_out, int out_size)
{
    const float* x     = (const float*)d_in[0];
    const float* Wqkv  = (const float*)d_in[1];
    const float* bqkv  = (const float*)d_in[2];
    const float* Wproj = (const float*)d_in[3];
    const float* bproj = (const float*)d_in[4];
    float* out = (float*)d_out;

    __nv_bfloat16 *xhi, *xlo, *wqh, *wql, *wph, *wpl, *qkvh, *qkvl, *ahi, *alo;
    cudaGetSymbolAddress((void**)&xhi, g_xhi);
    cudaGetSymbolAddress((void**)&xlo, g_xlo);
    cudaGetSymbolAddress((void**)&wqh, g_wqkvhi);
    cudaGetSymbolAddress((void**)&wql, g_wqkvlo);
    cudaGetSymbolAddress((void**)&wph, g_wprojhi);
    cudaGetSymbolAddress((void**)&wpl, g_wprojlo);
    cudaGetSymbolAddress((void**)&qkvh, g_qkvh);
    cudaGetSymbolAddress((void**)&qkvl, g_qkvl);
    cudaGetSymbolAddress((void**)&ahi, g_atthi);
    cudaGetSymbolAddress((void**)&alo, g_attlo);

    int nx = Mn * Cn / 4, nwq = Cn * 3 * Cn / 4, nwp = Cn * Cn / 4;
    pack_hilo_kernel<<<(nx + 255) / 256, 256>>>((const float4*)x, (uint2*)xhi, (uint2*)xlo, nx);
    pack_hilo_kernel<<<(nwq + 255) / 256, 256>>>((const float4*)Wqkv, (uint2*)wqh, (uint2*)wql, nwq);
    pack_hilo_kernel<<<(nwp + 255) / 256, 256>>>((const float4*)Wproj, (uint2*)wph, (uint2*)wpl, nwp);

    // 1) QKV = X @ W_qkv + b  -> hi/lo bf16
    gemm_bf16x3<1><<<dim3((3 * Cn) / 64, Mn / 128), 256>>>(
        (const uint4*)xhi, (const uint4*)xlo, (const uint4*)wqh, (const uint4*)wql,
        bqkv, nullptr, qkvh, qkvl, Mn, 3 * Cn, Cn);

    // 2) causal flash attention on tensor cores
    attn_mma_kernel<<<dim3(Tn / 64, Bn * Hn), 128>>>(qkvh, qkvl, ahi, alo);

    // 3) out = att @ W_proj + b  (fp32 out)
    gemm_bf16x3<0><<<dim3(Cn / 64, Mn / 128), 256>>>(
        (const uint4*)ahi, (const uint4*)alo, (const uint4*)wph, (const uint4*)wpl,
        bproj, out, nullptr, nullptr, Mn, Cn, Cn);
}

// round 8
// speedup vs baseline: 3.6928x; 1.2053x over previous
#include <cuda_runtime.h>
#include <cuda_bf16.h>
#include <cstdint>

#define Bn 4
#define Tn 2048
#define Cn 1024
#define Hn 16
#define Mn (Bn * Tn)

// ---------------- scratch (__device__ globals, no runtime alloc) ------------
__device__ __align__(16) __nv_bfloat16 g_xhi[(size_t)Mn * Cn];
__device__ __align__(16) __nv_bfloat16 g_xlo[(size_t)Mn * Cn];
__device__ __align__(16) __nv_bfloat16 g_wqkvhi[(size_t)Cn * 3 * Cn];  // [K][N]
__device__ __align__(16) __nv_bfloat16 g_wqkvlo[(size_t)Cn * 3 * Cn];
__device__ __align__(16) __nv_bfloat16 g_wprojhi[(size_t)Cn * Cn];
__device__ __align__(16) __nv_bfloat16 g_wprojlo[(size_t)Cn * Cn];
__device__ __align__(16) __nv_bfloat16 g_qkvh[(size_t)Mn * 3 * Cn];
__device__ __align__(16) __nv_bfloat16 g_qkvl[(size_t)Mn * 3 * Cn];
__device__ __align__(16) __nv_bfloat16 g_atthi[(size_t)Mn * Cn];
__device__ __align__(16) __nv_bfloat16 g_attlo[(size_t)Mn * Cn];

// ---------------- helpers ----------------------------------------------------
__device__ __forceinline__ uint32_t pk_bf16x2(float lo, float hi) {
    uint32_t r;
    asm("cvt.rn.bf16x2.f32 %0, %1, %2;" : "=r"(r) : "f"(hi), "f"(lo));
    return r;
}
__device__ __forceinline__ float bflow(uint32_t h)  { return __uint_as_float(h << 16); }
__device__ __forceinline__ float bfhigh(uint32_t h) { return __uint_as_float(h & 0xffff0000u); }

__device__ __forceinline__ void ldsm4(uint32_t& r0, uint32_t& r1, uint32_t& r2,
                                      uint32_t& r3, uint32_t a) {
    asm volatile("ldmatrix.sync.aligned.m8n8.x4.shared.b16 {%0,%1,%2,%3}, [%4];"
                 : "=r"(r0), "=r"(r1), "=r"(r2), "=r"(r3) : "r"(a));
}
__device__ __forceinline__ void ldsm4t(uint32_t& r0, uint32_t& r1, uint32_t& r2,
                                       uint32_t& r3, uint32_t a) {
    asm volatile("ldmatrix.sync.aligned.m8n8.x4.trans.shared.b16 {%0,%1,%2,%3}, [%4];"
                 : "=r"(r0), "=r"(r1), "=r"(r2), "=r"(r3) : "r"(a));
}
__device__ __forceinline__ void hmma(float d[4], const uint32_t a[4], const uint32_t b[2]) {
    asm volatile(
        "mma.sync.aligned.m16n8k16.row.col.f32.bf16.bf16.f32 "
        "{%0,%1,%2,%3}, {%4,%5,%6,%7}, {%8,%9}, {%0,%1,%2,%3};"
        : "+f"(d[0]), "+f"(d[1]), "+f"(d[2]), "+f"(d[3])
        : "r"(a[0]), "r"(a[1]), "r"(a[2]), "r"(a[3]), "r"(b[0]), "r"(b[1]));
}
__device__ __forceinline__ void cpa16(uint32_t s, const void* g) {
    asm volatile("cp.async.cg.shared.global [%0], [%1], 16;" :: "r"(s), "l"(g) : "memory");
}

// ---------------- pack fp32 -> hi/lo bf16 (row-major) ------------------------
__global__ __launch_bounds__(256)
void pack_hilo_kernel(const float4* __restrict__ in, uint2* __restrict__ ohi,
                      uint2* __restrict__ olo, int n4)
{
    int i = blockIdx.x * 256 + threadIdx.x;
    if (i >= n4) return;
    float4 v = in[i];
    uint32_t h0 = pk_bf16x2(v.x, v.y);
    uint32_t h1 = pk_bf16x2(v.z, v.w);
    ohi[i] = make_uint2(h0, h1);
    olo[i] = make_uint2(pk_bf16x2(v.x - bflow(h0), v.y - bfhigh(h0)),
                        pk_bf16x2(v.z - bflow(h1), v.w - bfhigh(h1)));
}

// ---------------- bf16x3 HMMA GEMM, 64x64 warp tiles ---------------------------
// C[M,N] = (Ahi+Alo)[M,K] @ (Bhi+Blo)[K,N] + bias.
// Block 128x128, 4 warps (2M x 2N), warp tile 64x64, K chunks of 32,
// cp.async double buffer. A smem: [m][16 words] XOR swizzle f=(m&6)<<1.
// B smem: [k][136 words] (272B rows). ldmatrix:HMMA = 16:96 per k16.
// OUT_MODE 0: fp32 + bias. OUT_MODE 1: hi/lo bf16 split + bias.
#define ABUF 8192
#define BBUF 8704
#define STAGE (2 * ABUF + 2 * BBUF)      // 33792
#define GEMM_SMEM (2 * STAGE)            // 67584

template <int OUT_MODE>
__global__ __launch_bounds__(128, 2)
void gemm_hmma64(const uint4* __restrict__ Ahi, const uint4* __restrict__ Alo,
                 const uint4* __restrict__ Bhi, const uint4* __restrict__ Blo,
                 const float* __restrict__ bias, float* __restrict__ Cm,
                 __nv_bfloat16* __restrict__ Chi, __nv_bfloat16* __restrict__ Clo,
                 int M, int N, int K)
{
    extern __shared__ __align__(1024) char dsm[];
    const int tid  = threadIdx.x;
    const int lane = tid & 31;
    const int warp = tid >> 5;
    const int wm   = warp >> 1;            // 0..1
    const int wn   = warp & 1;             // 0..1
    const int row0 = blockIdx.y * 128;
    const int col0 = blockIdx.x * 128;
    const uint32_t sb0 = (uint32_t)__cvta_generic_to_shared(dsm);

    const int NT = K >> 5;                 // 32-wide k chunks
    const int Kv = K >> 3;                 // A row stride (uint4)
    const int Nv = N >> 3;                 // B row stride (uint4)

    // writers
    const int ar = tid >> 2;               // A row 0..31 (+32*i)
    const int ag = tid & 3;                // A 16B group
    const int bkr = tid >> 4;              // B k-row 0..7 (+8*i)
    const int bc  = tid & 15;              // B 16B col

    // ldmatrix geometry (round-4 validated mappings)
    const int L  = lane;
    const int fr = (L & 7) + ((L >> 3) & 1) * 8;
    const int fa = ((L & 7) & 6) << 1;
    const uint32_t aoff = (uint32_t)(((wm * 64 + fr) * 16 + ((4 * (L >> 4)) ^ fa)) * 4);
    const uint32_t boff = (uint32_t)(fr * 272 + (wn * 64 + (L >> 4) * 8) * 2);

    auto load_chunk = [&](int ck) {
        uint32_t sb = sb0 + (uint32_t)((ck & 1) * STAGE);
#pragma unroll
        for (int i = 0; i < 4; i++) {
            int m = ar + i * 32;
            int f = (m & 6) << 1;
            uint32_t so = (uint32_t)((m * 16 + ((4 * ag) ^ f)) * 4);
            size_t ga = (size_t)(row0 + m) * Kv + ck * 4 + ag;
            cpa16(sb + so,        Ahi + ga);
            cpa16(sb + ABUF + so, Alo + ga);
        }
#pragma unroll
        for (int i = 0; i < 4; i++) {
            int kr = bkr + i * 8;
            uint32_t so = (uint32_t)(kr * 272 + bc * 16);
            size_t gb = (size_t)(ck * 32 + kr) * Nv + (col0 >> 3) + bc;
            cpa16(sb + 2 * ABUF + so,        Bhi + gb);
            cpa16(sb + 2 * ABUF + BBUF + so, Blo + gb);
        }
        asm volatile("cp.async.commit_group;" ::: "memory");
    };

    float acc[4][8][4];
#pragma unroll
    for (int mi = 0; mi < 4; mi++)
#pragma unroll
        for (int na = 0; na < 8; na++)
#pragma unroll
            for (int r = 0; r < 4; r++) acc[mi][na][r] = 0.0f;

    load_chunk(0);

    for (int kt = 0; kt < NT; kt++) {
        if (kt + 1 < NT) {
            load_chunk(kt + 1);
            asm volatile("cp.async.wait_group 1;" ::: "memory");
        } else {
            asm volatile("cp.async.wait_group 0;" ::: "memory");
        }
        __syncthreads();

        uint32_t sa = sb0 + (uint32_t)((kt & 1) * STAGE);
        uint32_t sbB = sa + 2 * ABUF;

#pragma unroll
        for (int ks = 0; ks < 2; ks++) {
            const uint32_t ax = (uint32_t)(ks * 32);
            uint32_t a_hi[4][4], a_lo[4][4];
#pragma unroll
            for (int mi = 0; mi < 4; mi++) {
                uint32_t ad = (sa + aoff + (uint32_t)(mi * 1024)) ^ ax;
                ldsm4(a_hi[mi][0], a_hi[mi][1], a_hi[mi][2], a_hi[mi][3], ad);
                ldsm4(a_lo[mi][0], a_lo[mi][1], a_lo[mi][2], a_lo[mi][3], ad + ABUF);
            }
#pragma unroll
            for (int nh = 0; nh < 2; nh++) {
                uint32_t bd = sbB + boff + (uint32_t)(nh * 64 + ks * 4352);
                uint32_t b_hi[4][2], b_lo[4][2];
                ldsm4t(b_hi[0][0], b_hi[0][1], b_hi[1][0], b_hi[1][1], bd);
                ldsm4t(b_hi[2][0], b_hi[2][1], b_hi[3][0], b_hi[3][1], bd + 32);
                ldsm4t(b_lo[0][0], b_lo[0][1], b_lo[1][0], b_lo[1][1], bd + BBUF);
                ldsm4t(b_lo[2][0], b_lo[2][1], b_lo[3][0], b_lo[3][1], bd + BBUF + 32);
#pragma unroll
                for (int mi = 0; mi < 4; mi++)
#pragma unroll
                    for (int ni = 0; ni < 4; ni++) {
                        float* d = acc[mi][nh * 4 + ni];
                        hmma(d, a_hi[mi], b_hi[ni]);
                        hmma(d, a_hi[mi], b_lo[ni]);
                        hmma(d, a_lo[mi], b_hi[ni]);
                    }
            }
        }
        __syncthreads();
    }

    // ---- epilogue ----
    const int g = lane >> 2, qd = lane & 3;
#pragma unroll
    for (int mi = 0; mi < 4; mi++) {
        int row = row0 + wm * 64 + mi * 16 + g;
#pragma unroll
        for (int na = 0; na < 8; na++) {
            int col = col0 + wn * 64 + na * 8 + 2 * qd;
            float2 bv = *(const float2*)&bias[col];
            float v0 = acc[mi][na][0] + bv.x, v1 = acc[mi][na][1] + bv.y;
            float v2 = acc[mi][na][2] + bv.x, v3 = acc[mi][na][3] + bv.y;
            if (OUT_MODE == 0) {
                *(float2*)&Cm[(size_t)row * N + col]       = make_float2(v0, v1);
                *(float2*)&Cm[(size_t)(row + 8) * N + col] = make_float2(v2, v3);
            } else {
                uint32_t hh = pk_bf16x2(v0, v1);
                size_t i0 = ((size_t)row * N + col) >> 1;
                ((uint32_t*)Chi)[i0] = hh;
                ((uint32_t*)Clo)[i0] = pk_bf16x2(v0 - bflow(hh), v1 - bfhigh(hh));
                hh = pk_bf16x2(v2, v3);
                size_t i1 = ((size_t)(row + 8) * N + col) >> 1;
                ((uint32_t*)Chi)[i1] = hh;
                ((uint32_t*)Clo)[i1] = pk_bf16x2(v2 - bflow(hh), v3 - bfhigh(hh));
            }
        }
    }
}

// ---------------- tensor-core flash attention (bf16x3, causal) ----------------
// (unchanged from round 6 — passing at ~320us)
__global__ __launch_bounds__(128)
void attn_mma_kernel(const __nv_bfloat16* __restrict__ qh,
                     const __nv_bfloat16* __restrict__ ql,
                     __nv_bfloat16* __restrict__ atthi,
                     __nv_bfloat16* __restrict__ attlo)
{
    __shared__ __align__(16) __nv_bfloat16 sKh[64 * 72], sKl[64 * 72];
    __shared__ __align__(16) __nv_bfloat16 sVh[64 * 72], sVl[64 * 72];

    const int tid  = threadIdx.x;
    const int lane = tid & 31;
    const int warp = tid >> 5;
    const int qt   = (int)(gridDim.x - 1) - (int)blockIdx.x;
    const int bh   = blockIdx.y;
    const int b    = bh >> 4, h = bh & 15;
    const int q0   = qt * 64;
    const int m0w  = warp * 16;
    const int g    = lane >> 2, qd = lane & 3;
    const size_t rowbase = (size_t)b * Tn;
    const int hcol = h * 64;

    const int fr = (lane & 7) + ((lane >> 3) & 1) * 8;
    const int hb = (lane >> 4) * 16;

    uint32_t sKh_b = (uint32_t)__cvta_generic_to_shared(sKh);
    uint32_t sKl_b = (uint32_t)__cvta_generic_to_shared(sKl);
    uint32_t sVh_b = (uint32_t)__cvta_generic_to_shared(sVh);
    uint32_t sVl_b = (uint32_t)__cvta_generic_to_shared(sVl);

#pragma unroll
    for (int it = 0; it < 4; it++) {
        int idx = tid + it * 128;
        int r = idx >> 3, c = idx & 7;
        size_t grow = (rowbase + q0 + r) * (3 * Cn) + hcol;
        ((uint4*)sKh)[r * 9 + c] = *((const uint4*)(qh + grow) + c);
        ((uint4*)sKl)[r * 9 + c] = *((const uint4*)(ql + grow) + c);
    }
    __syncthreads();

    uint32_t qhi[4][4], qlo[4][4];
#pragma unroll
    for (int j = 0; j < 4; j++) {
        uint32_t ad = (uint32_t)((m0w + fr) * 144 + j * 32 + hb);
        ldsm4(qhi[j][0], qhi[j][1], qhi[j][2], qhi[j][3], sKh_b + ad);
        ldsm4(qlo[j][0], qlo[j][1], qlo[j][2], qlo[j][3], sKl_b + ad);
    }

    float o[8][4];
#pragma unroll
    for (int nt = 0; nt < 8; nt++)
#pragma unroll
        for (int r = 0; r < 4; r++) o[nt][r] = 0.0f;
    float m0r = -1e30f, m1r = -1e30f, l0 = 0.0f, l1 = 0.0f;

    const float scale = 0.125f;
    const int rl0 = m0w + g, rl1 = rl0 + 8;

    for (int t = 0; t <= qt; t++) {
        const int kv0 = t * 64;
        __syncthreads();
#pragma unroll
        for (int it = 0; it < 4; it++) {
            int idx = tid + it * 128;
            int r = idx >> 3, c = idx & 7;
            size_t grow = (rowbase + kv0 + r) * (3 * Cn) + hcol;
            ((uint4*)sKh)[r * 9 + c] = *((const uint4*)(qh + grow + Cn) + c);
            ((uint4*)sKl)[r * 9 + c] = *((const uint4*)(ql + grow + Cn) + c);
            ((uint4*)sVh)[r * 9 + c] = *((const uint4*)(qh + grow + 2 * Cn) + c);
            ((uint4*)sVl)[r * 9 + c] = *((const uint4*)(ql + grow + 2 * Cn) + c);
        }
        __syncthreads();

        float s[8][4];
#pragma unroll
        for (int nt = 0; nt < 8; nt++)
#pragma unroll
            for (int r = 0; r < 4; r++) s[nt][r] = 0.0f;

#pragma unroll
        for (int p = 0; p < 4; p++) {
#pragma unroll
            for (int j = 0; j < 4; j++) {
                uint32_t kh0, kh1, kh2, kh3, kl0, kl1, kl2, kl3;
                uint32_t ad = (uint32_t)((p * 16 + fr) * 144 + j * 32 + hb);
                ldsm4(kh0, kh1, kh2, kh3, sKh_b + ad);
                ldsm4(kl0, kl1, kl2, kl3, sKl_b + ad);
                uint32_t b0h[2] = {kh0, kh2}, b1h[2] = {kh1, kh3};
                uint32_t b0l[2] = {kl0, kl2}, b1l[2] = {kl1, kl3};
                hmma(s[2 * p],     qhi[j], b0h);
                hmma(s[2 * p],     qhi[j], b0l);
                hmma(s[2 * p],     qlo[j], b0h);
                hmma(s[2 * p + 1], qhi[j], b1h);
                hmma(s[2 * p + 1], qhi[j], b1l);
                hmma(s[2 * p + 1], qlo[j], b1h);
            }
        }

#pragma unroll
        for (int nt = 0; nt < 8; nt++) {
            s[nt][0] *= scale; s[nt][1] *= scale;
            s[nt][2] *= scale; s[nt][3] *= scale;
        }
        if (t == qt) {
#pragma unroll
            for (int nt = 0; nt < 8; nt++) {
                int c0 = nt * 8 + 2 * qd;
                if (c0     > rl0) s[nt][0] = -1e30f;
                if (c0 + 1 > rl0) s[nt][1] = -1e30f;
                if (c0     > rl1) s[nt][2] = -1e30f;
                if (c0 + 1 > rl1) s[nt][3] = -1e30f;
            }
        }

        float mx0 = -1e30f, mx1 = -1e30f;
#pragma unroll
        for (int nt = 0; nt < 8; nt++) {
            mx0 = fmaxf(mx0, fmaxf(s[nt][0], s[nt][1]));
            mx1 = fmaxf(mx1, fmaxf(s[nt][2], s[nt][3]));
        }
        mx0 = fmaxf(mx0, __shfl_xor_sync(0xffffffffu, mx0, 1));
        mx0 = fmaxf(mx0, __shfl_xor_sync(0xffffffffu, mx0, 2));
        mx1 = fmaxf(mx1, __shfl_xor_sync(0xffffffffu, mx1, 1));
        mx1 = fmaxf(mx1, __shfl_xor_sync(0xffffffffu, mx1, 2));
        float mn0 = fmaxf(m0r, mx0), mn1 = fmaxf(m1r, mx1);
        float cf0 = __expf(m0r - mn0), cf1 = __expf(m1r - mn1);
        m0r = mn0; m1r = mn1;
        float sum0 = 0.0f, sum1 = 0.0f;
#pragma unroll
        for (int nt = 0; nt < 8; nt++) {
            s[nt][0] = __expf(s[nt][0] - mn0); sum0 += s[nt][0];
            s[nt][1] = __expf(s[nt][1] - mn0); sum0 += s[nt][1];
            s[nt][2] = __expf(s[nt][2] - mn1); sum1 += s[nt][2];
            s[nt][3] = __expf(s[nt][3] - mn1); sum1 += s[nt][3];
        }
        sum0 += __shfl_xor_sync(0xffffffffu, sum0, 1);
        sum0 += __shfl_xor_sync(0xffffffffu, sum0, 2);
        sum1 += __shfl_xor_sync(0xffffffffu, sum1, 1);
        sum1 += __shfl_xor_sync(0xffffffffu, sum1, 2);
        l0 = l0 * cf0 + sum0;
        l1 = l1 * cf1 + sum1;
#pragma unroll
        for (int nt = 0; nt < 8; nt++) {
            o[nt][0] *= cf0; o[nt][1] *= cf0;
            o[nt][2] *= cf1; o[nt][3] *= cf1;
        }

#pragma unroll
        for (int j = 0; j < 4; j++) {
            uint32_t phi[4], plo[4];
            uint32_t hh;
            hh = pk_bf16x2(s[2 * j][0], s[2 * j][1]);
            phi[0] = hh;
            plo[0] = pk_bf16x2(s[2 * j][0] - bflow(hh), s[2 * j][1] - bfhigh(hh));
            hh = pk_bf16x2(s[2 * j][2], s[2 * j][3]);
            phi[1] = hh;
            plo[1] = pk_bf16x2(s[2 * j][2] - bflow(hh), s[2 * j][3] - bfhigh(hh));
            hh = pk_bf16x2(s[2 * j + 1][0], s[2 * j + 1][1]);
            phi[2] = hh;
            plo[2] = pk_bf16x2(s[2 * j + 1][0] - bflow(hh), s[2 * j + 1][1] - bfhigh(hh));
            hh = pk_bf16x2(s[2 * j + 1][2], s[2 * j + 1][3]);
            phi[3] = hh;
            plo[3] = pk_bf16x2(s[2 * j + 1][2] - bflow(hh), s[2 * j + 1][3] - bfhigh(hh));

#pragma unroll
            for (int p = 0; p < 4; p++) {
                uint32_t v0, v1, v2, v3, w0, w1, w2, w3;
                uint32_t ad = (uint32_t)((j * 16 + fr) * 144 + p * 32 + hb);
                ldsm4t(v0, v1, v2, v3, sVh_b + ad);
                ldsm4t(w0, w1, w2, w3, sVl_b + ad);
                uint32_t bh0[2] = {v0, v1}, bh1[2] = {v2, v3};
                uint32_t bl0[2] = {w0, w1}, bl1[2] = {w2, w3};
                hmma(o[2 * p],     phi, bh0);
                hmma(o[2 * p],     phi, bl0);
                hmma(o[2 * p],     plo, bh0);
                hmma(o[2 * p + 1], phi, bh1);
                hmma(o[2 * p + 1], phi, bl1);
                hmma(o[2 * p + 1], plo, bh1);
            }
        }
    }

    float inv0 = 1.0f / l0, inv1 = 1.0f / l1;
    size_t orow0 = (rowbase + q0 + m0w + g) * Cn + hcol;
    size_t orow1 = orow0 + (size_t)8 * Cn;
#pragma unroll
    for (int nt = 0; nt < 8; nt++) {
        int c = nt * 8 + 2 * qd;
        float v0 = o[nt][0] * inv0, v1 = o[nt][1] * inv0;
        uint32_t hh = pk_bf16x2(v0, v1);
        ((uint32_t*)atthi)[(orow0 + c) >> 1] = hh;
        ((uint32_t*)attlo)[(orow0 + c) >> 1] =
            pk_bf16x2(v0 - bflow(hh), v1 - bfhigh(hh));
        v0 = o[nt][2] * inv1; v1 = o[nt][3] * inv1;
        hh = pk_bf16x2(v0, v1);
        ((uint32_t*)atthi)[(orow1 + c) >> 1] = hh;
        ((uint32_t*)attlo)[(orow1 + c) >> 1] =
            pk_bf16x2(v0 - bflow(hh), v1 - bfhigh(hh));
    }
}

// ---------------------------------------------------------------------------
extern "C" void kernel_launch(void* const* d_in, const int* in_sizes, int n_in,
                              void* d_out, int out_size)
{
    const float* x     = (const float*)d_in[0];
    const float* Wqkv  = (const float*)d_in[1];
    const float* bqkv  = (const float*)d_in[2];
    const float* Wproj = (const float*)d_in[3];
    const float* bproj = (const float*)d_in[4];
    float* out = (float*)d_out;

    __nv_bfloat16 *xhi, *xlo, *wqh, *wql, *wph, *wpl, *qkvh, *qkvl, *ahi, *alo;
    cudaGetSymbolAddress((void**)&xhi, g_xhi);
    cudaGetSymbolAddress((void**)&xlo, g_xlo);
    cudaGetSymbolAddress((void**)&wqh, g_wqkvhi);
    cudaGetSymbolAddress((void**)&wql, g_wqkvlo);
    cudaGetSymbolAddress((void**)&wph, g_wprojhi);
    cudaGetSymbolAddress((void**)&wpl, g_wprojlo);
    cudaGetSymbolAddress((void**)&qkvh, g_qkvh);
    cudaGetSymbolAddress((void**)&qkvl, g_qkvl);
    cudaGetSymbolAddress((void**)&ahi, g_atthi);
    cudaGetSymbolAddress((void**)&alo, g_attlo);

    cudaFuncSetAttribute(gemm_hmma64<0>, cudaFuncAttributeMaxDynamicSharedMemorySize, GEMM_SMEM);
    cudaFuncSetAttribute(gemm_hmma64<1>, cudaFuncAttributeMaxDynamicSharedMemorySize, GEMM_SMEM);

    // packs: all hi/lo bf16, row-major (weights stay [K][N])
    int nx = Mn * Cn / 4, nwq = Cn * 3 * Cn / 4, nwp = Cn * Cn / 4;
    pack_hilo_kernel<<<(nx + 255) / 256, 256>>>((const float4*)x, (uint2*)xhi, (uint2*)xlo, nx);
    pack_hilo_kernel<<<(nwq + 255) / 256, 256>>>((const float4*)Wqkv, (uint2*)wqh, (uint2*)wql, nwq);
    pack_hilo_kernel<<<(nwp + 255) / 256, 256>>>((const float4*)Wproj, (uint2*)wph, (uint2*)wpl, nwp);

    // 1) QKV = X @ W_qkv + b  -> hi/lo bf16
    gemm_hmma64<1><<<dim3(3 * Cn / 128, Mn / 128), 128, GEMM_SMEM>>>(
        (const uint4*)xhi, (const uint4*)xlo, (const uint4*)wqh, (const uint4*)wql,
        bqkv, nullptr, qkvh, qkvl, Mn, 3 * Cn, Cn);

    // 2) causal flash attention (mma.sync bf16x3)
    attn_mma_kernel<<<dim3(Tn / 64, Bn * Hn), 128>>>(qkvh, qkvl, ahi, alo);

    // 3) out = att @ W_proj + b  (fp32 out)
    gemm_hmma64<0><<<dim3(Cn / 128, Mn / 128), 128, GEMM_SMEM>>>(
        (const uint4*)ahi, (const uint4*)alo, (const uint4*)wph, (const uint4*)wpl,
        bproj, out, nullptr, nullptr, Mn, Cn, Cn);
}